// round 3
// baseline (speedup 1.0000x reference)
#include <cuda_runtime.h>

#define EPSV  1e-8f
#define SLOPE 0.01f
#define HID   32

__device__ __forceinline__ float lrelu(float x) { return x >= 0.0f ? x : SLOPE * x; }

__global__ __launch_bounds__(256)
void aero_kernel(const float* __restrict__ v, const float* __restrict__ w,
                 const float* __restrict__ W1, const float* __restrict__ b1,
                 const float* __restrict__ W2, const float* __restrict__ b2,
                 const float* __restrict__ Wd1, const float* __restrict__ bd1,
                 const float* __restrict__ Wd2, const float* __restrict__ bd2,
                 const float* __restrict__ bias,
                 float* __restrict__ out, int n)
{
    // Weights staged once per CTA. 32x32 matrices are stored TRANSPOSED so the
    // inner j-loop reads contiguous floats -> compiler emits LDS.128 broadcasts.
    __shared__ float sW1[HID * 3], sb1[HID];
    __shared__ float sW2t[HID * HID], sb2[HID];
    __shared__ float sWd1t[HID * HID], sbd1[HID];
    __shared__ float sWd2[3 * HID], sbd2[3], sbias[3];

    const int tid = threadIdx.x;
    for (int i = tid; i < HID * 3; i += blockDim.x) sW1[i] = W1[i];
    for (int i = tid; i < HID; i += blockDim.x) {
        sb1[i] = b1[i]; sb2[i] = b2[i]; sbd1[i] = bd1[i];
    }
    for (int i = tid; i < HID * HID; i += blockDim.x) {
        int j = i / HID, k = i % HID;
        sW2t[k * HID + j]  = W2[i];   // sW2t[k][j]  = W2[j][k]
        sWd1t[k * HID + j] = Wd1[i];
    }
    for (int i = tid; i < 3 * HID; i += blockDim.x) sWd2[i] = Wd2[i];
    if (tid < 3) { sbd2[tid] = bd2[tid]; sbias[tid] = bias[tid]; }
    __syncthreads();

    const int idx = blockIdx.x * blockDim.x + tid;
    if (idx >= n) return;

    const float vx = v[idx * 3 + 0], vy = v[idx * 3 + 1], vz = v[idx * 3 + 2];
    const float wx = w[idx * 3 + 0], wy = w[idx * 3 + 1], wz = w[idx * 3 + 2];

    // Gram-Schmidt (closed form; matches reference arithmetic incl. EPS placement)
    const float nv  = sqrtf(fmaf(vx, vx, fmaf(vy, vy, vz * vz)));
    const float iv  = 1.0f / (nv + EPSV);
    const float v0 = vx * iv, v1 = vy * iv, v2 = vz * iv;
    const float d  = fmaf(wx, v0, fmaf(wy, v1, wz * v2));       // w . v_on
    const float ox = fmaf(-d, v0, wx);
    const float oy = fmaf(-d, v1, wy);
    const float oz = fmaf(-d, v2, wz);
    const float nw = sqrtf(fmaf(ox, ox, fmaf(oy, oy, oz * oz)));
    const float iw = 1.0f / (nw + EPSV);
    const float w0 = ox * iw, w1 = oy * iw, w2 = oz * iw;
    const float u0 = fmaf(v1, w2, -v2 * w1);                    // v_on x w_on
    const float u1 = fmaf(v2, w0, -v0 * w2);
    const float u2 = fmaf(v0, w1, -v1 * w0);

    // feat = [v.v_on, w.v_on, w.w_on]  (v_local[0], w_local[0], w_local[1])
    const float f0 = fmaf(vx, v0, fmaf(vy, v1, vz * v2));
    const float f1 = d;
    const float f2 = fmaf(wx, w0, fmaf(wy, w1, wz * w2));

    // Layer 1: h1 = lrelu(feat @ W1^T + b1)
    float h1r[HID];
    #pragma unroll
    for (int j = 0; j < HID; j++) {
        float a = fmaf(f0, sW1[j * 3 + 0],
                  fmaf(f1, sW1[j * 3 + 1],
                  fmaf(f2, sW1[j * 3 + 2], sb1[j])));
        h1r[j] = lrelu(a);
    }

    // Layer 2: h = lrelu(h1 @ W2^T + b2) * h1
    float acc[HID];
    #pragma unroll
    for (int j = 0; j < HID; j++) acc[j] = sb2[j];
    #pragma unroll
    for (int k = 0; k < HID; k++) {
        const float a = h1r[k];
        const float4* wr = reinterpret_cast<const float4*>(&sW2t[k * HID]);
        #pragma unroll
        for (int j4 = 0; j4 < HID / 4; j4++) {
            float4 wv = wr[j4];
            acc[j4 * 4 + 0] = fmaf(a, wv.x, acc[j4 * 4 + 0]);
            acc[j4 * 4 + 1] = fmaf(a, wv.y, acc[j4 * 4 + 1]);
            acc[j4 * 4 + 2] = fmaf(a, wv.z, acc[j4 * 4 + 2]);
            acc[j4 * 4 + 3] = fmaf(a, wv.w, acc[j4 * 4 + 3]);
        }
    }
    #pragma unroll
    for (int j = 0; j < HID; j++) h1r[j] = lrelu(acc[j]) * h1r[j];

    // Layer 3: g = lrelu(h @ Wd1^T + bd1)
    #pragma unroll
    for (int j = 0; j < HID; j++) acc[j] = sbd1[j];
    #pragma unroll
    for (int k = 0; k < HID; k++) {
        const float a = h1r[k];
        const float4* wr = reinterpret_cast<const float4*>(&sWd1t[k * HID]);
        #pragma unroll
        for (int j4 = 0; j4 < HID / 4; j4++) {
            float4 wv = wr[j4];
            acc[j4 * 4 + 0] = fmaf(a, wv.x, acc[j4 * 4 + 0]);
            acc[j4 * 4 + 1] = fmaf(a, wv.y, acc[j4 * 4 + 1]);
            acc[j4 * 4 + 2] = fmaf(a, wv.z, acc[j4 * 4 + 2]);
            acc[j4 * 4 + 3] = fmaf(a, wv.w, acc[j4 * 4 + 3]);
        }
    }

    // Layer 4: y = g @ Wd2^T + bd2  (3 outputs)
    float y0 = sbd2[0], y1 = sbd2[1], y2 = sbd2[2];
    #pragma unroll
    for (int k = 0; k < HID; k++) {
        const float g = lrelu(acc[k]);
        y0 = fmaf(g, sWd2[0 * HID + k], y0);
        y1 = fmaf(g, sWd2[1 * HID + k], y1);
        y2 = fmaf(g, sWd2[2 * HID + k], y2);
    }

    // out = R @ y + bias, R columns = (v_on, w_on, u_on)
    out[idx * 3 + 0] = fmaf(v0, y0, fmaf(w0, y1, fmaf(u0, y2, sbias[0])));
    out[idx * 3 + 1] = fmaf(v1, y0, fmaf(w1, y1, fmaf(u1, y2, sbias[1])));
    out[idx * 3 + 2] = fmaf(v2, y0, fmaf(w2, y1, fmaf(u2, y2, sbias[2])));
}

extern "C" void kernel_launch(void* const* d_in, const int* in_sizes, int n_in,
                              void* d_out, int out_size)
{
    const float* v    = (const float*)d_in[0];
    const float* w    = (const float*)d_in[1];
    const float* W1   = (const float*)d_in[2];
    const float* b1   = (const float*)d_in[3];
    const float* W2   = (const float*)d_in[4];
    const float* b2   = (const float*)d_in[5];
    const float* Wd1  = (const float*)d_in[6];
    const float* bd1  = (const float*)d_in[7];
    const float* Wd2  = (const float*)d_in[8];
    const float* bd2  = (const float*)d_in[9];
    const float* bias = (const float*)d_in[10];
    float* out = (float*)d_out;

    const int n = in_sizes[0] / 3;
    const int threads = 256;
    const int blocks = (n + threads - 1) / threads;
    aero_kernel<<<blocks, threads>>>(v, w, W1, b1, W2, b2, Wd1, bd1,
                                     Wd2, bd2, bias, out, n);
}